// round 16
// baseline (speedup 1.0000x reference)
#include <cuda_runtime.h>
#include <cuda_fp16.h>
#include <cstdint>

#define EPS 1e-5f

__device__ __forceinline__ unsigned tanh2(unsigned v) {
    unsigned y; asm("tanh.approx.f16x2 %0,%1;" : "=r"(y) : "r"(v)); return y;
}
__device__ __forceinline__ unsigned packh2(float a, float b) {
    __half2 h = __floats2half2_rn(a, b);
    return *reinterpret_cast<unsigned*>(&h);
}
__device__ __forceinline__ float2 h2f2(unsigned u) {
    __half2 h = *reinterpret_cast<__half2*>(&u);
    return __half22float2(h);
}
__device__ __forceinline__ unsigned hfma2u(unsigned a, unsigned b, unsigned c) {
    __half2 r = __hfma2(*reinterpret_cast<__half2*>(&a),
                        *reinterpret_cast<__half2*>(&b),
                        *reinterpret_cast<__half2*>(&c));
    return *reinterpret_cast<unsigned*>(&r);
}
__device__ __forceinline__ unsigned hadd2u(unsigned a, unsigned b) {
    __half2 r = __hadd2(*reinterpret_cast<__half2*>(&a), *reinterpret_cast<__half2*>(&b));
    return *reinterpret_cast<unsigned*>(&r);
}
__device__ __forceinline__ unsigned hmul2u(unsigned a, unsigned b) {
    __half2 r = __hmul2(*reinterpret_cast<__half2*>(&a), *reinterpret_cast<__half2*>(&b));
    return *reinterpret_cast<unsigned*>(&r);
}
__device__ __forceinline__ unsigned splat2(float v) {
    __half2 h = __float2half2_rn(v);
    return *reinterpret_cast<unsigned*>(&h);
}

// f16-accumulator MMA: D/C are 2 packed half2 regs.
__device__ __forceinline__ void mma16h(unsigned* d,
                                       unsigned a0, unsigned a1, unsigned a2, unsigned a3,
                                       unsigned b0, unsigned b1) {
    asm volatile(
        "mma.sync.aligned.m16n8k16.row.col.f16.f16.f16.f16 "
        "{%0,%1},{%2,%3,%4,%5},{%6,%7},{%0,%1};"
        : "+r"(d[0]), "+r"(d[1])
        : "r"(a0), "r"(a1), "r"(a2), "r"(a3), "r"(b0), "r"(b1));
}

__device__ __forceinline__ void ldsm4(unsigned& r0, unsigned& r1, unsigned& r2, unsigned& r3,
                                      unsigned addr) {
    asm volatile("ldmatrix.sync.aligned.m8n8.x4.shared.b16 {%0,%1,%2,%3},[%4];"
                 : "=r"(r0), "=r"(r1), "=r"(r2), "=r"(r3) : "r"(addr));
}

// hb row stride: 72 halfs = 36 u32 words (conflict-free, proven)
#define HSTRW 36
#define MT 4   // 4 x 16 rows = 64 edges per warp tile

__device__ __forceinline__ void init_bias_h(unsigned d[MT][8][2],
                                            const unsigned* __restrict__ sbh, int tg) {
#pragma unroll
    for (int nt = 0; nt < 8; nt++) {
        unsigned u = sbh[4 * nt + tg];
#pragma unroll
        for (int mt = 0; mt < MT; mt++) { d[mt][nt][0] = u; d[mt][nt][1] = u; }
    }
}

template <int NKK>
__device__ __forceinline__ void mma_layer_h(unsigned d[MT][8][2], const uint4* __restrict__ bf,
                                            const unsigned* a_bases, int lane) {
#pragma unroll
    for (int kk = 0; kk < NKK; kk++) {
        unsigned A[MT][4];
#pragma unroll
        for (int mt = 0; mt < MT; mt++)
            ldsm4(A[mt][0], A[mt][1], A[mt][2], A[mt][3], a_bases[mt] + kk * 32);
#pragma unroll
        for (int ntp = 0; ntp < 4; ntp++) {
            uint4 b = bf[(kk * 4 + ntp) * 32 + lane];
#pragma unroll
            for (int mt = 0; mt < MT; mt++) {
                mma16h(d[mt][2 * ntp],     A[mt][0], A[mt][1], A[mt][2], A[mt][3], b.x, b.y);
                mma16h(d[mt][2 * ntp + 1], A[mt][0], A[mt][1], A[mt][2], A[mt][3], b.z, b.w);
            }
        }
    }
}

// half2 stats trees (unpack once), half2 apply, tanh2 -> hb.
__device__ __forceinline__ void ln_store_h2(unsigned d[MT][8][2],
                                            const unsigned* __restrict__ G2,
                                            const unsigned* __restrict__ BE2,
                                            unsigned* __restrict__ hbu, int g, int tg) {
#pragma unroll
    for (int mt = 0; mt < MT; mt++) {
        unsigned sa0 = d[mt][0][0], sa1 = d[mt][0][1];
        unsigned qa0 = hmul2u(d[mt][0][0], d[mt][0][0]);
        unsigned qa1 = hmul2u(d[mt][0][1], d[mt][0][1]);
#pragma unroll
        for (int nt = 1; nt < 8; nt++) {
            sa0 = hadd2u(sa0, d[mt][nt][0]);
            sa1 = hadd2u(sa1, d[mt][nt][1]);
            qa0 = hfma2u(d[mt][nt][0], d[mt][nt][0], qa0);
            qa1 = hfma2u(d[mt][nt][1], d[mt][nt][1], qa1);
        }
        float2 fs0 = h2f2(sa0), fq0 = h2f2(qa0);
        float2 fs1 = h2f2(sa1), fq1 = h2f2(qa1);
        float s1 = fs0.x + fs0.y, q1 = fq0.x + fq0.y;
        float s2 = fs1.x + fs1.y, q2 = fq1.x + fq1.y;
        s1 += __shfl_xor_sync(0xffffffffu, s1, 1); q1 += __shfl_xor_sync(0xffffffffu, q1, 1);
        s2 += __shfl_xor_sync(0xffffffffu, s2, 1); q2 += __shfl_xor_sync(0xffffffffu, q2, 1);
        s1 += __shfl_xor_sync(0xffffffffu, s1, 2); q1 += __shfl_xor_sync(0xffffffffu, q1, 2);
        s2 += __shfl_xor_sync(0xffffffffu, s2, 2); q2 += __shfl_xor_sync(0xffffffffu, q2, 2);
        float m1 = s1 * (1.f / 64.f), m2 = s2 * (1.f / 64.f);
        float i1 = rsqrtf(fmaf(-m1, m1, q1 * (1.f / 64.f)) + EPS);
        float i2 = rsqrtf(fmaf(-m2, m2, q2 * (1.f / 64.f)) + EPS);
        unsigned I1 = splat2(i1), MI1 = splat2(-m1 * i1);
        unsigned I2 = splat2(i2), MI2 = splat2(-m2 * i2);
#pragma unroll
        for (int nt = 0; nt < 8; nt++) {
            unsigned G = G2[4 * nt + tg], BE = BE2[4 * nt + tg];
            unsigned y0 = hfma2u(hfma2u(d[mt][nt][0], I1, MI1), G, BE);
            unsigned y1 = hfma2u(hfma2u(d[mt][nt][1], I2, MI2), G, BE);
            hbu[(16 * mt + g) * HSTRW + 4 * nt + tg]     = tanh2(y0);
            hbu[(16 * mt + g + 8) * HSTRW + 4 * nt + tg] = tanh2(y1);
        }
    }
}

// smem layout (float units):
// BF0 [512] @0 | BF1 [2048] @512 | BF2 [2048] @2560
// sbh0/1/2 (32 u32) @4608,4640,4672
// G2_0@4704 BE2_0@4736 G2_1@4768 BE2_1@4800 G2_2@4832 BE2_2@4864 (32 u32 each)
// sw3@4896 (64 f32) -> 4960
// hb @4960: 4 warps x 64 rows x 36 words = 9216 -> total 14176 (~55.4 KB)
#define SMEM_FLOATS 14176

__global__ __launch_bounds__(128, 4) void edge_mlp_tc(
    const float* __restrict__ x, const int* __restrict__ ei,
    const float* __restrict__ W0, const float* __restrict__ b0,
    const float* __restrict__ g0, const float* __restrict__ be0,
    const float* __restrict__ W1, const float* __restrict__ b1,
    const float* __restrict__ g1, const float* __restrict__ be1,
    const float* __restrict__ W2, const float* __restrict__ b2,
    const float* __restrict__ g2, const float* __restrict__ be2,
    const float* __restrict__ W3, const float* __restrict__ b3,
    float* __restrict__ out, int n_edges)
{
    extern __shared__ float sm[];
    uint4* BF0 = (uint4*)(sm);
    uint4* BF1 = (uint4*)(sm + 512);
    uint4* BF2 = (uint4*)(sm + 2560);
    unsigned* sbh0 = (unsigned*)(sm + 4608);
    unsigned* sbh1 = (unsigned*)(sm + 4640);
    unsigned* sbh2 = (unsigned*)(sm + 4672);
    unsigned* G2_0 = (unsigned*)(sm + 4704);
    unsigned* BE2_0 = (unsigned*)(sm + 4736);
    unsigned* G2_1 = (unsigned*)(sm + 4768);
    unsigned* BE2_1 = (unsigned*)(sm + 4800);
    unsigned* G2_2 = (unsigned*)(sm + 4832);
    unsigned* BE2_2 = (unsigned*)(sm + 4864);
    float* sw3 = sm + 4896;

    const int tid = threadIdx.x;

    if (tid < 128) {   // BF0: kk=0 only
        int ntp = tid >> 5, ln = tid & 31, gg = ln >> 2, tt = ln & 3;
        int k0 = 2 * tt;
        int n0 = 8 * (2 * ntp) + gg, n1 = 8 * (2 * ntp + 1) + gg;
        BF0[tid] = make_uint4(
            packh2(W0[k0 * 64 + n0],       W0[(k0 + 1) * 64 + n0]),
            packh2(W0[(k0 + 8) * 64 + n0], W0[(k0 + 9) * 64 + n0]),
            packh2(W0[k0 * 64 + n1],       W0[(k0 + 1) * 64 + n1]),
            packh2(W0[(k0 + 8) * 64 + n1], W0[(k0 + 9) * 64 + n1]));
    }
    for (int i = tid; i < 512; i += 128) {   // BF1/BF2: kk=0..3
        int kk = i >> 7, ntp = (i >> 5) & 3, ln = i & 31, gg = ln >> 2, tt = ln & 3;
        int k0 = 16 * kk + 2 * tt;
        int n0 = 8 * (2 * ntp) + gg, n1 = 8 * (2 * ntp + 1) + gg;
        BF1[i] = make_uint4(
            packh2(W1[k0 * 64 + n0],       W1[(k0 + 1) * 64 + n0]),
            packh2(W1[(k0 + 8) * 64 + n0], W1[(k0 + 9) * 64 + n0]),
            packh2(W1[k0 * 64 + n1],       W1[(k0 + 1) * 64 + n1]),
            packh2(W1[(k0 + 8) * 64 + n1], W1[(k0 + 9) * 64 + n1]));
        BF2[i] = make_uint4(
            packh2(W2[k0 * 64 + n0],       W2[(k0 + 1) * 64 + n0]),
            packh2(W2[(k0 + 8) * 64 + n0], W2[(k0 + 9) * 64 + n0]),
            packh2(W2[k0 * 64 + n1],       W2[(k0 + 1) * 64 + n1]),
            packh2(W2[(k0 + 8) * 64 + n1], W2[(k0 + 9) * 64 + n1]));
    }
    if (tid < 32) {   // packed half2 params, layout [4*nt+tg] -> cols {8nt+2tg, 8nt+2tg+1}
        int nt = tid >> 2, tg4 = tid & 3;
        int n0 = 8 * nt + 2 * tg4;
        sbh0[tid] = packh2(b0[n0], b0[n0 + 1]);
        sbh1[tid] = packh2(b1[n0], b1[n0 + 1]);
        sbh2[tid] = packh2(b2[n0], b2[n0 + 1]);
        G2_0[tid]  = packh2(g0[n0], g0[n0 + 1]);
        BE2_0[tid] = packh2(be0[n0], be0[n0 + 1]);
        G2_1[tid]  = packh2(g1[n0], g1[n0 + 1]);
        BE2_1[tid] = packh2(be1[n0], be1[n0 + 1]);
        G2_2[tid]  = packh2(g2[n0], g2[n0 + 1]);
        BE2_2[tid] = packh2(be2[n0], be2[n0 + 1]);
    }
    if (tid < 64) sw3[tid] = W3[tid];
    __syncthreads();
    const float b3v = b3[0];

    const int lane = tid & 31, wid = tid >> 5;
    const int g = lane >> 2, tg = lane & 3;
    unsigned* hbu = (unsigned*)(sm + 4960) + wid * (64 * HSTRW);
    const float4* x4 = (const float4*)x;

    const int lrow = lane & 15;
    const int lc4 = ((lane >> 4) & 1) * 4;
    unsigned a_bases[MT];
#pragma unroll
    for (int mt = 0; mt < MT; mt++)
        a_bases[mt] = (unsigned)__cvta_generic_to_shared(&hbu[(16 * mt + lrow) * HSTRW + lc4]);

    const int tile_stride = gridDim.x * 4 * 64;
    for (int base = (blockIdx.x * 4 + wid) * 64; base < n_edges; base += tile_stride) {
        // gather 64 edges: lane handles rows `lane` and `lane+32`
#pragma unroll
        for (int rr = 0; rr < 2; rr++) {
            int r = lane + 32 * rr;
            int e = base + r; if (e >= n_edges) e = n_edges - 1;
            int si = ei[e], di = ei[n_edges + e];
            float4 A0 = x4[2 * si], A1 = x4[2 * si + 1];
            float4 C0 = x4[2 * di], C1 = x4[2 * di + 1];
            unsigned* hr = &hbu[r * HSTRW];
            *(uint4*)&hr[0] = make_uint4(packh2(A0.x, A0.y), packh2(A0.z, A0.w),
                                         packh2(A1.x, A1.y), packh2(A1.z, A1.w));
            *(uint4*)&hr[4] = make_uint4(packh2(C0.x, C0.y), packh2(C0.z, C0.w),
                                         packh2(C1.x, C1.y), packh2(C1.z, C1.w));
        }
        __syncwarp();

        unsigned d[MT][8][2];

        // layer 0: K=16
        init_bias_h(d, sbh0, tg);
        mma_layer_h<1>(d, BF0, a_bases, lane);
        __syncwarp();
        ln_store_h2(d, G2_0, BE2_0, hbu, g, tg);
        __syncwarp();

        // layer 1: K=64
        init_bias_h(d, sbh1, tg);
        mma_layer_h<4>(d, BF1, a_bases, lane);
        __syncwarp();
        ln_store_h2(d, G2_1, BE2_1, hbu, g, tg);
        __syncwarp();

        // layer 2: K=64; f32 stats, half2 apply + tanh2, f32 dot (output protected)
        init_bias_h(d, sbh2, tg);
        mma_layer_h<4>(d, BF2, a_bases, lane);
        __syncwarp();   // hb reads done -> safe to overwrite next iteration
#pragma unroll
        for (int mt = 0; mt < MT; mt++) {
            float s1 = 0.f, q1 = 0.f, s2 = 0.f, q2 = 0.f;
#pragma unroll
            for (int nt = 0; nt < 8; nt++) {
                float2 lo = h2f2(d[mt][nt][0]);
                float2 hi = h2f2(d[mt][nt][1]);
                s1 += lo.x + lo.y; q1 = fmaf(lo.x, lo.x, q1); q1 = fmaf(lo.y, lo.y, q1);
                s2 += hi.x + hi.y; q2 = fmaf(hi.x, hi.x, q2); q2 = fmaf(hi.y, hi.y, q2);
            }
            s1 += __shfl_xor_sync(0xffffffffu, s1, 1); q1 += __shfl_xor_sync(0xffffffffu, q1, 1);
            s2 += __shfl_xor_sync(0xffffffffu, s2, 1); q2 += __shfl_xor_sync(0xffffffffu, q2, 1);
            s1 += __shfl_xor_sync(0xffffffffu, s1, 2); q1 += __shfl_xor_sync(0xffffffffu, q1, 2);
            s2 += __shfl_xor_sync(0xffffffffu, s2, 2); q2 += __shfl_xor_sync(0xffffffffu, q2, 2);
            float m1 = s1 * (1.f / 64.f), m2 = s2 * (1.f / 64.f);
            float i1 = rsqrtf(fmaf(-m1, m1, q1 * (1.f / 64.f)) + EPS);
            float i2 = rsqrtf(fmaf(-m2, m2, q2 * (1.f / 64.f)) + EPS);
            unsigned I1 = splat2(i1), MI1 = splat2(-m1 * i1);
            unsigned I2 = splat2(i2), MI2 = splat2(-m2 * i2);
            float p1 = 0.f, p2 = 0.f;
#pragma unroll
            for (int nt = 0; nt < 8; nt++) {
                unsigned G = G2_2[4 * nt + tg], BE = BE2_2[4 * nt + tg];
                unsigned y0 = tanh2(hfma2u(hfma2u(d[mt][nt][0], I1, MI1), G, BE));
                unsigned y1 = tanh2(hfma2u(hfma2u(d[mt][nt][1], I2, MI2), G, BE));
                float2 t01 = h2f2(y0), t23 = h2f2(y1);
                float2 w = *(const float2*)&sw3[8 * nt + 2 * tg];
                p1 = fmaf(t01.x, w.x, p1); p1 = fmaf(t01.y, w.y, p1);
                p2 = fmaf(t23.x, w.x, p2); p2 = fmaf(t23.y, w.y, p2);
            }
            p1 += __shfl_xor_sync(0xffffffffu, p1, 1); p1 += __shfl_xor_sync(0xffffffffu, p1, 2);
            p2 += __shfl_xor_sync(0xffffffffu, p2, 1); p2 += __shfl_xor_sync(0xffffffffu, p2, 2);
            if (tg == 0) {
                int e1 = base + 16 * mt + g, e2 = e1 + 8;
                if (e1 < n_edges) out[e1] = p1 + b3v;
                if (e2 < n_edges) out[e2] = p2 + b3v;
            }
        }
        __syncwarp();
    }
}

extern "C" void kernel_launch(void* const* d_in, const int* in_sizes, int n_in,
                              void* d_out, int out_size) {
    const float* x   = (const float*)d_in[0];
    const int*   ei  = (const int*)d_in[1];
    const float* W0 = (const float*)d_in[2];
    const float* b0 = (const float*)d_in[3];
    const float* g0 = (const float*)d_in[4];
    const float* be0 = (const float*)d_in[5];
    const float* W1 = (const float*)d_in[6];
    const float* b1 = (const float*)d_in[7];
    const float* g1 = (const float*)d_in[8];
    const float* be1 = (const float*)d_in[9];
    const float* W2 = (const float*)d_in[10];
    const float* b2 = (const float*)d_in[11];
    const float* g2 = (const float*)d_in[12];
    const float* be2 = (const float*)d_in[13];
    const float* W3 = (const float*)d_in[14];
    const float* b3 = (const float*)d_in[15];
    float* out = (float*)d_out;

    const int n_edges = in_sizes[1] / 2;
    const size_t smem_bytes = SMEM_FLOATS * sizeof(float);  // ~55.4 KB

    static bool attr_set = false;
    if (!attr_set) {
        cudaFuncSetAttribute(edge_mlp_tc, cudaFuncAttributeMaxDynamicSharedMemorySize,
                             (int)smem_bytes);
        attr_set = true;
    }

    const int threads = 128;
    const int blocks = 148 * 4;  // 4 resident blocks/SM target (16 warps), grid-stride
    edge_mlp_tc<<<blocks, threads, smem_bytes>>>(x, ei,
                                                 W0, b0, g0, be0,
                                                 W1, b1, g1, be1,
                                                 W2, b2, g2, be2,
                                                 W3, b3, out, n_edges);
}

// round 17
// speedup vs baseline: 1.0812x; 1.0812x over previous
#include <cuda_runtime.h>
#include <cuda_fp16.h>
#include <cstdint>

#define EPS 1e-5f

__device__ __forceinline__ unsigned tanh2(unsigned v) {
    unsigned y; asm("tanh.approx.f16x2 %0,%1;" : "=r"(y) : "r"(v)); return y;
}
__device__ __forceinline__ unsigned packh2(float a, float b) {
    __half2 h = __floats2half2_rn(a, b);
    return *reinterpret_cast<unsigned*>(&h);
}
__device__ __forceinline__ float2 h2f2(unsigned u) {
    __half2 h = *reinterpret_cast<__half2*>(&u);
    return __half22float2(h);
}
__device__ __forceinline__ unsigned hfma2u(unsigned a, unsigned b, unsigned c) {
    __half2 r = __hfma2(*reinterpret_cast<__half2*>(&a),
                        *reinterpret_cast<__half2*>(&b),
                        *reinterpret_cast<__half2*>(&c));
    return *reinterpret_cast<unsigned*>(&r);
}
__device__ __forceinline__ unsigned hadd2u(unsigned a, unsigned b) {
    __half2 r = __hadd2(*reinterpret_cast<__half2*>(&a), *reinterpret_cast<__half2*>(&b));
    return *reinterpret_cast<unsigned*>(&r);
}
__device__ __forceinline__ unsigned hmul2u(unsigned a, unsigned b) {
    __half2 r = __hmul2(*reinterpret_cast<__half2*>(&a), *reinterpret_cast<__half2*>(&b));
    return *reinterpret_cast<unsigned*>(&r);
}
__device__ __forceinline__ unsigned splat2(float v) {
    __half2 h = __float2half2_rn(v);
    return *reinterpret_cast<unsigned*>(&h);
}

// f16-accumulator MMA: D/C are 2 packed half2 regs.
__device__ __forceinline__ void mma16h(unsigned* d,
                                       unsigned a0, unsigned a1, unsigned a2, unsigned a3,
                                       unsigned b0, unsigned b1) {
    asm volatile(
        "mma.sync.aligned.m16n8k16.row.col.f16.f16.f16.f16 "
        "{%0,%1},{%2,%3,%4,%5},{%6,%7},{%0,%1};"
        : "+r"(d[0]), "+r"(d[1])
        : "r"(a0), "r"(a1), "r"(a2), "r"(a3), "r"(b0), "r"(b1));
}

__device__ __forceinline__ void ldsm4(unsigned& r0, unsigned& r1, unsigned& r2, unsigned& r3,
                                      unsigned addr) {
    asm volatile("ldmatrix.sync.aligned.m8n8.x4.shared.b16 {%0,%1,%2,%3},[%4];"
                 : "=r"(r0), "=r"(r1), "=r"(r2), "=r"(r3) : "r"(addr));
}

// hb row stride: 72 halfs = 36 u32 words (conflict-free, proven)
#define HSTRW 36

__device__ __forceinline__ void init_bias_h(unsigned d[2][8][2],
                                            const unsigned* __restrict__ sbh, int tg) {
#pragma unroll
    for (int nt = 0; nt < 8; nt++) {
        unsigned u = sbh[4 * nt + tg];
        d[0][nt][0] = u; d[0][nt][1] = u;
        d[1][nt][0] = u; d[1][nt][1] = u;
    }
}

template <int NKK>
__device__ __forceinline__ void mma_layer_h(unsigned d[2][8][2], const uint4* __restrict__ bf,
                                            unsigned a_base0, unsigned a_base1, int lane) {
#pragma unroll
    for (int kk = 0; kk < NKK; kk++) {
        unsigned A[2][4];
        ldsm4(A[0][0], A[0][1], A[0][2], A[0][3], a_base0 + kk * 32);
        ldsm4(A[1][0], A[1][1], A[1][2], A[1][3], a_base1 + kk * 32);
#pragma unroll
        for (int ntp = 0; ntp < 4; ntp++) {
            uint4 b = bf[(kk * 4 + ntp) * 32 + lane];
            mma16h(d[0][2 * ntp],     A[0][0], A[0][1], A[0][2], A[0][3], b.x, b.y);
            mma16h(d[1][2 * ntp],     A[1][0], A[1][1], A[1][2], A[1][3], b.x, b.y);
            mma16h(d[0][2 * ntp + 1], A[0][0], A[0][1], A[0][2], A[0][3], b.z, b.w);
            mma16h(d[1][2 * ntp + 1], A[1][0], A[1][1], A[1][2], A[1][3], b.z, b.w);
        }
    }
}

// half2 stats trees (unpack once), half2 apply, tanh2 -> hb. Layers 0/1.
__device__ __forceinline__ void ln_store_h2(unsigned d[2][8][2],
                                            const unsigned* __restrict__ G2,
                                            const unsigned* __restrict__ BE2,
                                            unsigned* __restrict__ hbu, int g, int tg) {
#pragma unroll
    for (int mt = 0; mt < 2; mt++) {
        unsigned sa0 = d[mt][0][0], sa1 = d[mt][0][1];
        unsigned qa0 = hmul2u(d[mt][0][0], d[mt][0][0]);
        unsigned qa1 = hmul2u(d[mt][0][1], d[mt][0][1]);
#pragma unroll
        for (int nt = 1; nt < 8; nt++) {
            sa0 = hadd2u(sa0, d[mt][nt][0]);
            sa1 = hadd2u(sa1, d[mt][nt][1]);
            qa0 = hfma2u(d[mt][nt][0], d[mt][nt][0], qa0);
            qa1 = hfma2u(d[mt][nt][1], d[mt][nt][1], qa1);
        }
        float2 fs0 = h2f2(sa0), fq0 = h2f2(qa0);
        float2 fs1 = h2f2(sa1), fq1 = h2f2(qa1);
        float s1 = fs0.x + fs0.y, q1 = fq0.x + fq0.y;
        float s2 = fs1.x + fs1.y, q2 = fq1.x + fq1.y;
        s1 += __shfl_xor_sync(0xffffffffu, s1, 1); q1 += __shfl_xor_sync(0xffffffffu, q1, 1);
        s2 += __shfl_xor_sync(0xffffffffu, s2, 1); q2 += __shfl_xor_sync(0xffffffffu, q2, 1);
        s1 += __shfl_xor_sync(0xffffffffu, s1, 2); q1 += __shfl_xor_sync(0xffffffffu, q1, 2);
        s2 += __shfl_xor_sync(0xffffffffu, s2, 2); q2 += __shfl_xor_sync(0xffffffffu, q2, 2);
        float m1 = s1 * (1.f / 64.f), m2 = s2 * (1.f / 64.f);
        float i1 = rsqrtf(fmaf(-m1, m1, q1 * (1.f / 64.f)) + EPS);
        float i2 = rsqrtf(fmaf(-m2, m2, q2 * (1.f / 64.f)) + EPS);
        unsigned I1 = splat2(i1), MI1 = splat2(-m1 * i1);
        unsigned I2 = splat2(i2), MI2 = splat2(-m2 * i2);
#pragma unroll
        for (int nt = 0; nt < 8; nt++) {
            unsigned G = G2[4 * nt + tg], BE = BE2[4 * nt + tg];
            unsigned y0 = hfma2u(hfma2u(d[mt][nt][0], I1, MI1), G, BE);
            unsigned y1 = hfma2u(hfma2u(d[mt][nt][1], I2, MI2), G, BE);
            hbu[(16 * mt + g) * HSTRW + 4 * nt + tg]     = tanh2(y0);
            hbu[(16 * mt + g + 8) * HSTRW + 4 * nt + tg] = tanh2(y1);
        }
    }
}

// smem layout (float units):
// BF0 [512] @0 | BF1 [2048] @512 | BF2 [2048] @2560
// sbh0/1/2 (32 u32) @4608,4640,4672
// G2_0@4704 BE2_0@4736 G2_1@4768 BE2_1@4800 G2_2@4832 BE2_2@4864 (32 u32 each)
// sw3@4896 (64 f32) -> 4960
// hb @4960: 4 warps x 32 rows x 36 words = 4608 -> total 9568 (~37.4 KB; x6 = 224.3 KB)
#define SMEM_FLOATS 9568

__global__ __launch_bounds__(128, 6) void edge_mlp_tc(
    const float* __restrict__ x, const int* __restrict__ ei,
    const float* __restrict__ W0, const float* __restrict__ b0,
    const float* __restrict__ g0, const float* __restrict__ be0,
    const float* __restrict__ W1, const float* __restrict__ b1,
    const float* __restrict__ g1, const float* __restrict__ be1,
    const float* __restrict__ W2, const float* __restrict__ b2,
    const float* __restrict__ g2, const float* __restrict__ be2,
    const float* __restrict__ W3, const float* __restrict__ b3,
    float* __restrict__ out, int n_edges)
{
    extern __shared__ float sm[];
    uint4* BF0 = (uint4*)(sm);
    uint4* BF1 = (uint4*)(sm + 512);
    uint4* BF2 = (uint4*)(sm + 2560);
    unsigned* sbh0 = (unsigned*)(sm + 4608);
    unsigned* sbh1 = (unsigned*)(sm + 4640);
    unsigned* sbh2 = (unsigned*)(sm + 4672);
    unsigned* G2_0 = (unsigned*)(sm + 4704);
    unsigned* BE2_0 = (unsigned*)(sm + 4736);
    unsigned* G2_1 = (unsigned*)(sm + 4768);
    unsigned* BE2_1 = (unsigned*)(sm + 4800);
    unsigned* G2_2 = (unsigned*)(sm + 4832);
    unsigned* BE2_2 = (unsigned*)(sm + 4864);
    float* sw3 = sm + 4896;

    const int tid = threadIdx.x;

    if (tid < 128) {   // BF0: kk=0 only
        int ntp = tid >> 5, ln = tid & 31, gg = ln >> 2, tt = ln & 3;
        int k0 = 2 * tt;
        int n0 = 8 * (2 * ntp) + gg, n1 = 8 * (2 * ntp + 1) + gg;
        BF0[tid] = make_uint4(
            packh2(W0[k0 * 64 + n0],       W0[(k0 + 1) * 64 + n0]),
            packh2(W0[(k0 + 8) * 64 + n0], W0[(k0 + 9) * 64 + n0]),
            packh2(W0[k0 * 64 + n1],       W0[(k0 + 1) * 64 + n1]),
            packh2(W0[(k0 + 8) * 64 + n1], W0[(k0 + 9) * 64 + n1]));
    }
    for (int i = tid; i < 512; i += 128) {   // BF1/BF2: kk=0..3
        int kk = i >> 7, ntp = (i >> 5) & 3, ln = i & 31, gg = ln >> 2, tt = ln & 3;
        int k0 = 16 * kk + 2 * tt;
        int n0 = 8 * (2 * ntp) + gg, n1 = 8 * (2 * ntp + 1) + gg;
        BF1[i] = make_uint4(
            packh2(W1[k0 * 64 + n0],       W1[(k0 + 1) * 64 + n0]),
            packh2(W1[(k0 + 8) * 64 + n0], W1[(k0 + 9) * 64 + n0]),
            packh2(W1[k0 * 64 + n1],       W1[(k0 + 1) * 64 + n1]),
            packh2(W1[(k0 + 8) * 64 + n1], W1[(k0 + 9) * 64 + n1]));
        BF2[i] = make_uint4(
            packh2(W2[k0 * 64 + n0],       W2[(k0 + 1) * 64 + n0]),
            packh2(W2[(k0 + 8) * 64 + n0], W2[(k0 + 9) * 64 + n0]),
            packh2(W2[k0 * 64 + n1],       W2[(k0 + 1) * 64 + n1]),
            packh2(W2[(k0 + 8) * 64 + n1], W2[(k0 + 9) * 64 + n1]));
    }
    if (tid < 32) {   // packed half2 params, layout [4*nt+tg] -> cols {8nt+2tg, 8nt+2tg+1}
        int nt = tid >> 2, tg4 = tid & 3;
        int n0 = 8 * nt + 2 * tg4;
        sbh0[tid] = packh2(b0[n0], b0[n0 + 1]);
        sbh1[tid] = packh2(b1[n0], b1[n0 + 1]);
        sbh2[tid] = packh2(b2[n0], b2[n0 + 1]);
        G2_0[tid]  = packh2(g0[n0], g0[n0 + 1]);
        BE2_0[tid] = packh2(be0[n0], be0[n0 + 1]);
        G2_1[tid]  = packh2(g1[n0], g1[n0 + 1]);
        BE2_1[tid] = packh2(be1[n0], be1[n0 + 1]);
        G2_2[tid]  = packh2(g2[n0], g2[n0 + 1]);
        BE2_2[tid] = packh2(be2[n0], be2[n0 + 1]);
    }
    if (tid < 64) sw3[tid] = W3[tid];
    __syncthreads();
    const float b3v = b3[0];

    const int lane = tid & 31, wid = tid >> 5;
    const int g = lane >> 2, tg = lane & 3;
    unsigned* hbu = (unsigned*)(sm + 4960) + wid * (32 * HSTRW);
    const float4* x4 = (const float4*)x;

    const int lrow = lane & 15;
    const int lc4 = ((lane >> 4) & 1) * 4;
    unsigned a_base0 = (unsigned)__cvta_generic_to_shared(&hbu[lrow * HSTRW + lc4]);
    unsigned a_base1 = (unsigned)__cvta_generic_to_shared(&hbu[(16 + lrow) * HSTRW + lc4]);

    const int tile_stride = gridDim.x * 4 * 32;
    for (int base = (blockIdx.x * 4 + wid) * 32; base < n_edges; base += tile_stride) {
        // gather 32 edges -> hb row `lane`, 16 halfs
        int e = base + lane; if (e >= n_edges) e = n_edges - 1;
        int si = ei[e], di = ei[n_edges + e];
        float4 A0 = x4[2 * si], A1 = x4[2 * si + 1];
        float4 C0 = x4[2 * di], C1 = x4[2 * di + 1];
        {
            unsigned* hr = &hbu[lane * HSTRW];
            *(uint4*)&hr[0] = make_uint4(packh2(A0.x, A0.y), packh2(A0.z, A0.w),
                                         packh2(A1.x, A1.y), packh2(A1.z, A1.w));
            *(uint4*)&hr[4] = make_uint4(packh2(C0.x, C0.y), packh2(C0.z, C0.w),
                                         packh2(C1.x, C1.y), packh2(C1.z, C1.w));
        }
        __syncwarp();

        unsigned d[2][8][2];

        // layer 0: K=16
        init_bias_h(d, sbh0, tg);
        mma_layer_h<1>(d, BF0, a_base0, a_base1, lane);
        __syncwarp();
        ln_store_h2(d, G2_0, BE2_0, hbu, g, tg);
        __syncwarp();

        // layer 1: K=64
        init_bias_h(d, sbh1, tg);
        mma_layer_h<4>(d, BF1, a_base0, a_base1, lane);
        __syncwarp();
        ln_store_h2(d, G2_1, BE2_1, hbu, g, tg);
        __syncwarp();

        // layer 2: K=64; f32 stats, half2 apply + tanh2, f32 dot (output protected)
        init_bias_h(d, sbh2, tg);
        mma_layer_h<4>(d, BF2, a_base0, a_base1, lane);
        __syncwarp();   // hb reads done -> safe to overwrite next iteration
#pragma unroll
        for (int mt = 0; mt < 2; mt++) {
            float s1 = 0.f, q1 = 0.f, s2 = 0.f, q2 = 0.f;
#pragma unroll
            for (int nt = 0; nt < 8; nt++) {
                float2 lo = h2f2(d[mt][nt][0]);
                float2 hi = h2f2(d[mt][nt][1]);
                s1 += lo.x + lo.y; q1 = fmaf(lo.x, lo.x, q1); q1 = fmaf(lo.y, lo.y, q1);
                s2 += hi.x + hi.y; q2 = fmaf(hi.x, hi.x, q2); q2 = fmaf(hi.y, hi.y, q2);
            }
            s1 += __shfl_xor_sync(0xffffffffu, s1, 1); q1 += __shfl_xor_sync(0xffffffffu, q1, 1);
            s2 += __shfl_xor_sync(0xffffffffu, s2, 1); q2 += __shfl_xor_sync(0xffffffffu, q2, 1);
            s1 += __shfl_xor_sync(0xffffffffu, s1, 2); q1 += __shfl_xor_sync(0xffffffffu, q1, 2);
            s2 += __shfl_xor_sync(0xffffffffu, s2, 2); q2 += __shfl_xor_sync(0xffffffffu, q2, 2);
            float m1 = s1 * (1.f / 64.f), m2 = s2 * (1.f / 64.f);
            float i1 = rsqrtf(fmaf(-m1, m1, q1 * (1.f / 64.f)) + EPS);
            float i2 = rsqrtf(fmaf(-m2, m2, q2 * (1.f / 64.f)) + EPS);
            unsigned I1 = splat2(i1), MI1 = splat2(-m1 * i1);
            unsigned I2 = splat2(i2), MI2 = splat2(-m2 * i2);
            float p1 = 0.f, p2 = 0.f;
#pragma unroll
            for (int nt = 0; nt < 8; nt++) {
                unsigned G = G2_2[4 * nt + tg], BE = BE2_2[4 * nt + tg];
                unsigned y0 = tanh2(hfma2u(hfma2u(d[mt][nt][0], I1, MI1), G, BE));
                unsigned y1 = tanh2(hfma2u(hfma2u(d[mt][nt][1], I2, MI2), G, BE));
                float2 t01 = h2f2(y0), t23 = h2f2(y1);
                float2 w = *(const float2*)&sw3[8 * nt + 2 * tg];
                p1 = fmaf(t01.x, w.x, p1); p1 = fmaf(t01.y, w.y, p1);
                p2 = fmaf(t23.x, w.x, p2); p2 = fmaf(t23.y, w.y, p2);
            }
            p1 += __shfl_xor_sync(0xffffffffu, p1, 1); p1 += __shfl_xor_sync(0xffffffffu, p1, 2);
            p2 += __shfl_xor_sync(0xffffffffu, p2, 1); p2 += __shfl_xor_sync(0xffffffffu, p2, 2);
            if (tg == 0) {
                int e1 = base + 16 * mt + g, e2 = e1 + 8;
                if (e1 < n_edges) out[e1] = p1 + b3v;
                if (e2 < n_edges) out[e2] = p2 + b3v;
            }
        }
        __syncwarp();
    }
}

extern "C" void kernel_launch(void* const* d_in, const int* in_sizes, int n_in,
                              void* d_out, int out_size) {
    const float* x   = (const float*)d_in[0];
    const int*   ei  = (const int*)d_in[1];
    const float* W0 = (const float*)d_in[2];
    const float* b0 = (const float*)d_in[3];
    const float* g0 = (const float*)d_in[4];
    const float* be0 = (const float*)d_in[5];
    const float* W1 = (const float*)d_in[6];
    const float* b1 = (const float*)d_in[7];
    const float* g1 = (const float*)d_in[8];
    const float* be1 = (const float*)d_in[9];
    const float* W2 = (const float*)d_in[10];
    const float* b2 = (const float*)d_in[11];
    const float* g2 = (const float*)d_in[12];
    const float* be2 = (const float*)d_in[13];
    const float* W3 = (const float*)d_in[14];
    const float* b3 = (const float*)d_in[15];
    float* out = (float*)d_out;

    const int n_edges = in_sizes[1] / 2;
    const size_t smem_bytes = SMEM_FLOATS * sizeof(float);  // ~37.4 KB

    static bool attr_set = false;
    if (!attr_set) {
        cudaFuncSetAttribute(edge_mlp_tc, cudaFuncAttributeMaxDynamicSharedMemorySize,
                             (int)smem_bytes);
        attr_set = true;
    }

    const int threads = 128;
    const int blocks = 148 * 6;  // 6 resident blocks/SM target (24 warps), grid-stride
    edge_mlp_tc<<<blocks, threads, smem_bytes>>>(x, ei,
                                                 W0, b0, g0, be0,
                                                 W1, b1, g1, be1,
                                                 W2, b2, g2, be2,
                                                 W3, b3, out, n_edges);
}